// round 1
// baseline (speedup 1.0000x reference)
#include <cuda_runtime.h>
#include <math.h>

#define BB 4
#define LL 2048
#define DD 1024
#define HH 16
#define DKK 64
#define BH (BB*HH)        // 64
#define MROWS (BB*LL)     // 8192

// ---------------- device scratch (allocation-free) ----------------
__device__ float g_q[BH * LL * DKK];     // [bh][l][dk]
__device__ float g_k[BH * LL * DKK];
__device__ float g_v[BH * LL * DKK];
__device__ float g_o[MROWS * DD];        // concat [b*L, D]
__device__ float g_attn_scratch[BH * LL * LL]; // fallback if attn not in d_out

// ---------------- projection GEMM: C = A @ W^T + bias ----------------
// A: [M, 1024] row-major, W: [1024, 1024] row-major (row n = weights of out-feature n)
// HEADED=1: scatter to [b,h,l,dk] layout; HEADED=0: flat [m, n]
template <int HEADED>
__global__ void proj_kernel(const float* __restrict__ A, const float* __restrict__ W,
                            const float* __restrict__ bias, float* __restrict__ out) {
    __shared__ float sA[16][65];  // sA[k][i]
    __shared__ float sB[16][65];  // sB[k][j]
    const int tid = threadIdx.x;
    const int tx = tid & 15, ty = tid >> 4;
    const int m0 = blockIdx.y * 64, n0 = blockIdx.x * 64;
    const int lk = tid & 15;
    const int li = (tid >> 4) * 4;

    float acc[4][4] = {};

    for (int k0 = 0; k0 < DD; k0 += 16) {
        #pragma unroll
        for (int r = 0; r < 4; r++) {
            sA[lk][li + r] = A[(size_t)(m0 + li + r) * DD + k0 + lk];
            sB[lk][li + r] = W[(size_t)(n0 + li + r) * DD + k0 + lk];
        }
        __syncthreads();
        #pragma unroll
        for (int k = 0; k < 16; k++) {
            float a[4], b[4];
            #pragma unroll
            for (int r = 0; r < 4; r++) a[r] = sA[k][ty + 16 * r];
            #pragma unroll
            for (int s = 0; s < 4; s++) b[s] = sB[k][tx + 16 * s];
            #pragma unroll
            for (int r = 0; r < 4; r++)
                #pragma unroll
                for (int s = 0; s < 4; s++)
                    acc[r][s] += a[r] * b[s];
        }
        __syncthreads();
    }

    #pragma unroll
    for (int r = 0; r < 4; r++) {
        const int m = m0 + ty + 16 * r;
        #pragma unroll
        for (int s = 0; s < 4; s++) {
            const int n = n0 + tx + 16 * s;
            const float v = acc[r][s] + bias[n];
            if (HEADED) {
                const int b = m >> 11, l = m & (LL - 1);
                const int h = n >> 6,  c = n & 63;
                out[(((size_t)(b * HH + h) * LL + l) * DKK) + c] = v;
            } else {
                out[(size_t)m * DD + n] = v;
            }
        }
    }
}

// ---------------- scores: S = Q K^T / 8, lower-triangular tiles only ----------------
__global__ void scores_kernel(const float* __restrict__ Q, const float* __restrict__ K,
                              float* __restrict__ attn) {
    const int kt = blockIdx.x, qt = blockIdx.y, bh = blockIdx.z;
    if (kt > qt) return;  // fully masked tile: softmax writes the zeros
    const int q0 = qt * 64, k0 = kt * 64;
    const float* Qb = Q + (size_t)bh * LL * DKK;
    const float* Kb = K + (size_t)bh * LL * DKK;

    __shared__ float sQ[64][65];  // sQ[k][i]
    __shared__ float sK[64][65];  // sK[k][j]
    const int tid = threadIdx.x;
    const int tx = tid & 15, ty = tid >> 4;

    #pragma unroll
    for (int it = 0; it < 4; it++) {
        const int row = (tid >> 4) + it * 16;
        const int c = (tid & 15) * 4;
        float4 q4 = *(const float4*)(Qb + (size_t)(q0 + row) * DKK + c);
        sQ[c + 0][row] = q4.x; sQ[c + 1][row] = q4.y;
        sQ[c + 2][row] = q4.z; sQ[c + 3][row] = q4.w;
        float4 k4 = *(const float4*)(Kb + (size_t)(k0 + row) * DKK + c);
        sK[c + 0][row] = k4.x; sK[c + 1][row] = k4.y;
        sK[c + 2][row] = k4.z; sK[c + 3][row] = k4.w;
    }
    __syncthreads();

    float acc[4][4] = {};
    #pragma unroll 16
    for (int k = 0; k < 64; k++) {
        float a[4], b[4];
        #pragma unroll
        for (int r = 0; r < 4; r++) a[r] = sQ[k][ty + 16 * r];
        #pragma unroll
        for (int s = 0; s < 4; s++) b[s] = sK[k][tx + 16 * s];
        #pragma unroll
        for (int r = 0; r < 4; r++)
            #pragma unroll
            for (int s = 0; s < 4; s++)
                acc[r][s] += a[r] * b[s];
    }

    float* outp = attn + ((size_t)bh * LL + q0) * LL + k0;
    #pragma unroll
    for (int r = 0; r < 4; r++)
        #pragma unroll
        for (int s = 0; s < 4; s++)
            outp[(size_t)(ty + 16 * r) * LL + tx + 16 * s] = acc[r][s] * 0.125f;
}

// ---------------- row softmax (causal: valid = row+1, zeros beyond) ----------------
__global__ void softmax_kernel(float* __restrict__ attn) {
    const int row = blockIdx.x, bh = blockIdx.y;
    float* p = attn + ((size_t)bh * LL + row) * LL;
    const int valid = row + 1;
    const int tid = threadIdx.x;

    __shared__ float sred[8];

    float4 v[2];
    float m = -3.4e38f;
    #pragma unroll
    for (int i = 0; i < 2; i++) {
        const int j = (tid + i * 256) * 4;
        v[i] = *(const float4*)(p + j);
        if (j + 0 < valid) m = fmaxf(m, v[i].x);
        if (j + 1 < valid) m = fmaxf(m, v[i].y);
        if (j + 2 < valid) m = fmaxf(m, v[i].z);
        if (j + 3 < valid) m = fmaxf(m, v[i].w);
    }
    // block max
    #pragma unroll
    for (int o = 16; o > 0; o >>= 1) m = fmaxf(m, __shfl_xor_sync(0xffffffff, m, o));
    if ((tid & 31) == 0) sred[tid >> 5] = m;
    __syncthreads();
    m = sred[0];
    #pragma unroll
    for (int w = 1; w < 8; w++) m = fmaxf(m, sred[w]);

    float sum = 0.0f;
    #pragma unroll
    for (int i = 0; i < 2; i++) {
        const int j = (tid + i * 256) * 4;
        v[i].x = (j + 0 < valid) ? __expf(v[i].x - m) : 0.0f;
        v[i].y = (j + 1 < valid) ? __expf(v[i].y - m) : 0.0f;
        v[i].z = (j + 2 < valid) ? __expf(v[i].z - m) : 0.0f;
        v[i].w = (j + 3 < valid) ? __expf(v[i].w - m) : 0.0f;
        sum += v[i].x + v[i].y + v[i].z + v[i].w;
    }
    __syncthreads();
    #pragma unroll
    for (int o = 16; o > 0; o >>= 1) sum += __shfl_xor_sync(0xffffffff, sum, o);
    if ((tid & 31) == 0) sred[tid >> 5] = sum;
    __syncthreads();
    sum = 0.0f;
    #pragma unroll
    for (int w = 0; w < 8; w++) sum += sred[w];
    const float inv = 1.0f / sum;

    #pragma unroll
    for (int i = 0; i < 2; i++) {
        const int j = (tid + i * 256) * 4;
        float4 o4;
        o4.x = v[i].x * inv; o4.y = v[i].y * inv;
        o4.z = v[i].z * inv; o4.w = v[i].w * inv;
        *(float4*)(p + j) = o4;
    }
}

// ---------------- O = P @ V (causal k-range), scatter to concat layout ----------------
__global__ void av_kernel(const float* __restrict__ attn, const float* __restrict__ V,
                          float* __restrict__ Ocat) {
    const int qt = blockIdx.x, bh = blockIdx.y;
    const int b = bh >> 4, h = bh & 15;
    const float* Pb = attn + (size_t)bh * LL * LL;
    const float* Vb = V + (size_t)bh * LL * DKK;

    __shared__ float sP[64][65];  // sP[k][q]
    __shared__ float sV[64][65];  // sV[k][c]
    const int tid = threadIdx.x;
    const int tx = tid & 15, ty = tid >> 4;
    const int q0 = qt * 64;

    float acc[4][4] = {};

    for (int kt = 0; kt <= qt; kt++) {
        const int k0 = kt * 64;
        #pragma unroll
        for (int it = 0; it < 4; it++) {
            const int row = (tid >> 4) + it * 16;
            const int c = (tid & 15) * 4;
            float4 p4 = *(const float4*)(Pb + (size_t)(q0 + row) * LL + k0 + c);
            sP[c + 0][row] = p4.x; sP[c + 1][row] = p4.y;
            sP[c + 2][row] = p4.z; sP[c + 3][row] = p4.w;
            float4 v4 = *(const float4*)(Vb + (size_t)(k0 + row) * DKK + c);
            sV[row][c + 0] = v4.x; sV[row][c + 1] = v4.y;
            sV[row][c + 2] = v4.z; sV[row][c + 3] = v4.w;
        }
        __syncthreads();
        #pragma unroll 16
        for (int k = 0; k < 64; k++) {
            float a[4], bb[4];
            #pragma unroll
            for (int r = 0; r < 4; r++) a[r] = sP[k][ty + 16 * r];
            #pragma unroll
            for (int s = 0; s < 4; s++) bb[s] = sV[k][tx + 16 * s];
            #pragma unroll
            for (int r = 0; r < 4; r++)
                #pragma unroll
                for (int s = 0; s < 4; s++)
                    acc[r][s] += a[r] * bb[s];
        }
        __syncthreads();
    }

    #pragma unroll
    for (int r = 0; r < 4; r++) {
        const int q = q0 + ty + 16 * r;
        #pragma unroll
        for (int s = 0; s < 4; s++) {
            const int c = tx + 16 * s;
            Ocat[(size_t)(b * LL + q) * DD + h * DKK + c] = acc[r][s];
        }
    }
}

// ---------------- launch ----------------
extern "C" void kernel_launch(void* const* d_in, const int* in_sizes, int n_in,
                              void* d_out, int out_size) {
    const float* x  = (const float*)d_in[0];
    // d_in[1] = mask (causal tril; structure exploited directly)
    const float* Wq = (const float*)d_in[2];
    const float* bq = (const float*)d_in[3];
    const float* Wk = (const float*)d_in[4];
    const float* bk = (const float*)d_in[5];
    const float* Wv = (const float*)d_in[6];
    const float* bv = (const float*)d_in[7];
    const float* Wo = (const float*)d_in[8];
    const float* bo = (const float*)d_in[9];
    float* out = (float*)d_out;

    const size_t out_elems  = (size_t)BB * LL * DD;           // 8388608
    const size_t attn_elems = (size_t)BH * LL * LL;           // 268435456

    float *q, *k, *v, *oc, *attn;
    cudaGetSymbolAddress((void**)&q,  g_q);
    cudaGetSymbolAddress((void**)&k,  g_k);
    cudaGetSymbolAddress((void**)&v,  g_v);
    cudaGetSymbolAddress((void**)&oc, g_o);
    if ((size_t)out_size >= out_elems + attn_elems) {
        attn = out + out_elems;   // attn_weights part of output: write in place
    } else {
        cudaGetSymbolAddress((void**)&attn, g_attn_scratch);
    }

    dim3 projGrid(DD / 64, MROWS / 64);       // (16, 128)
    proj_kernel<1><<<projGrid, 256>>>(x, Wq, bq, q);
    proj_kernel<1><<<projGrid, 256>>>(x, Wk, bk, k);
    proj_kernel<1><<<projGrid, 256>>>(x, Wv, bv, v);

    dim3 scoreGrid(LL / 64, LL / 64, BH);     // (32, 32, 64)
    scores_kernel<<<scoreGrid, 256>>>(q, k, attn);

    dim3 smGrid(LL, BH);                      // (2048, 64)
    softmax_kernel<<<smGrid, 256>>>(attn);

    dim3 avGrid(LL / 64, BH);                 // (32, 64)
    av_kernel<<<avGrid, 256>>>(attn, v, oc);

    proj_kernel<0><<<projGrid, 256>>>(oc, Wo, bo, out);
}

// round 3
// speedup vs baseline: 1.6182x; 1.6182x over previous
#include <cuda_runtime.h>
#include <cuda_bf16.h>
#include <cstdint>
#include <math.h>

#define BB 4
#define LL 2048
#define DD 1024
#define HH 16
#define DKK 64
#define BH (BB*HH)        // 64
#define MROWS (BB*LL)     // 8192

#define SPAD 40           // smem row stride (bf16 elems) for BK=32 tiles

// ---------------- device scratch (allocation-free) ----------------
__device__ float g_q[(size_t)BH * LL * DKK];     // [bh][l][dk]
__device__ float g_k[(size_t)BH * LL * DKK];
__device__ float g_vt[(size_t)BH * DKK * LL];    // [bh][dk][l]  (V transposed)
__device__ float g_oc[(size_t)MROWS * DD];       // concat attention output
__device__ float g_attn_scratch[(size_t)BH * LL * LL]; // fallback

// ---------------- mma helpers ----------------
__device__ __forceinline__ uint32_t s32(const void* p) {
    return (uint32_t)__cvta_generic_to_shared(p);
}

#define LDSM_X4(R, a)                                                          \
    asm volatile("ldmatrix.sync.aligned.m8n8.x4.shared.b16 {%0,%1,%2,%3}, [%4];" \
        : "=r"((R)[0]), "=r"((R)[1]), "=r"((R)[2]), "=r"((R)[3]) : "r"(a))
#define LDSM_X2(R, a)                                                          \
    asm volatile("ldmatrix.sync.aligned.m8n8.x2.shared.b16 {%0,%1}, [%2];"     \
        : "=r"((R)[0]), "=r"((R)[1]) : "r"(a))

__device__ __forceinline__ void mma_bf16(float* c, const uint32_t* a, const uint32_t* b) {
    asm volatile(
        "mma.sync.aligned.m16n8k16.row.col.f32.bf16.bf16.f32 "
        "{%0,%1,%2,%3}, {%4,%5,%6,%7}, {%8,%9}, {%0,%1,%2,%3};"
        : "+f"(c[0]), "+f"(c[1]), "+f"(c[2]), "+f"(c[3])
        : "r"(a[0]), "r"(a[1]), "r"(a[2]), "r"(a[3]), "r"(b[0]), "r"(b[1]));
}

// Load [nrows x 32] fp32 chunk (row stride ld), split to bf16 hi/lo in smem.
__device__ __forceinline__ void load_split32(__nv_bfloat16* shi, __nv_bfloat16* slo,
                                             const float* __restrict__ g, int ld,
                                             int nrows, int tid) {
    const int units = nrows * 8;
    for (int u = tid; u < units; u += 256) {
        const int r = u >> 3, c4 = (u & 7) << 2;
        float4 v = *(const float4*)(g + (size_t)r * ld + c4);
        __nv_bfloat16 h0 = __float2bfloat16(v.x), h1 = __float2bfloat16(v.y);
        __nv_bfloat16 h2 = __float2bfloat16(v.z), h3 = __float2bfloat16(v.w);
        __nv_bfloat16 l0 = __float2bfloat16(v.x - __bfloat162float(h0));
        __nv_bfloat16 l1 = __float2bfloat16(v.y - __bfloat162float(h1));
        __nv_bfloat16 l2 = __float2bfloat16(v.z - __bfloat162float(h2));
        __nv_bfloat16 l3 = __float2bfloat16(v.w - __bfloat162float(h3));
        uint2 hv, lv;
        hv.x = ((uint32_t)__bfloat16_as_ushort(h1) << 16) | __bfloat16_as_ushort(h0);
        hv.y = ((uint32_t)__bfloat16_as_ushort(h3) << 16) | __bfloat16_as_ushort(h2);
        lv.x = ((uint32_t)__bfloat16_as_ushort(l1) << 16) | __bfloat16_as_ushort(l0);
        lv.y = ((uint32_t)__bfloat16_as_ushort(l3) << 16) | __bfloat16_as_ushort(l2);
        *(uint2*)(shi + r * SPAD + c4) = hv;
        *(uint2*)(slo + r * SPAD + c4) = lv;
    }
}

// One BK=32 step: 3-pass split-bf16 MMA over the block tile.
template <int MT, int NT>
__device__ __forceinline__ void block_mma_k32(
    const __nv_bfloat16* sAh, const __nv_bfloat16* sAl,
    const __nv_bfloat16* sBh, const __nv_bfloat16* sBl,
    int a_row0, int b_row0, int lane, float (&acc)[MT][NT][4]) {
    #pragma unroll
    for (int kb = 0; kb < 32; kb += 16) {
        uint32_t ah[MT][4], al[MT][4], bh[NT][2], bl[NT][2];
        const int ar = a_row0 + (lane & 15);
        const int ac = kb + ((lane >> 4) << 3);
        #pragma unroll
        for (int i = 0; i < MT; i++) {
            LDSM_X4(ah[i], s32(sAh + (ar + i * 16) * SPAD + ac));
            LDSM_X4(al[i], s32(sAl + (ar + i * 16) * SPAD + ac));
        }
        const int br = b_row0 + (lane & 7);
        const int bc = kb + (((lane >> 3) & 1) << 3);
        #pragma unroll
        for (int j = 0; j < NT; j++) {
            LDSM_X2(bh[j], s32(sBh + (br + j * 8) * SPAD + bc));
            LDSM_X2(bl[j], s32(sBl + (br + j * 8) * SPAD + bc));
        }
        #pragma unroll
        for (int i = 0; i < MT; i++)
            #pragma unroll
            for (int j = 0; j < NT; j++) {
                mma_bf16(acc[i][j], ah[i], bh[j]);
                mma_bf16(acc[i][j], ah[i], bl[j]);
                mma_bf16(acc[i][j], al[i], bh[j]);
            }
    }
}

// Stage one warp-column group of accumulators into fp32 smem [128][33].
template <int MT, int NT>
__device__ __forceinline__ void stage_group(float* stg, int warp_m, int lane,
                                            float (&acc)[MT][NT][4], float scale) {
    const int r0 = warp_m * MT * 16 + (lane >> 2);
    const int c0 = (lane & 3) * 2;
    #pragma unroll
    for (int i = 0; i < MT; i++)
        #pragma unroll
        for (int j = 0; j < NT; j++) {
            float* p = stg + (size_t)(r0 + i * 16) * 33 + j * 8 + c0;
            p[0] = acc[i][j][0] * scale;
            p[1] = acc[i][j][1] * scale;
            p[8 * 33 + 0] = acc[i][j][2] * scale;
            p[8 * 33 + 1] = acc[i][j][3] * scale;
        }
}

// ================= projection GEMM: C = A @ W^T + bias =================
// MODE 0: headed   out[((b*16+h)*2048 + l)*64 + c]
// MODE 1: V^T      out[((b*16+h)*64 + c)*2048 + l]
// MODE 2: flat     out[m*1024 + n]
template <int MODE>
__global__ void __launch_bounds__(256)
gemm_proj(const float* __restrict__ A, const float* __restrict__ W,
          const float* __restrict__ bias, float* __restrict__ out) {
    __shared__ __align__(16) char sraw[40960];
    __nv_bfloat16* sAh = (__nv_bfloat16*)(sraw);
    __nv_bfloat16* sAl = (__nv_bfloat16*)(sraw + 10240);
    __nv_bfloat16* sBh = (__nv_bfloat16*)(sraw + 20480);
    __nv_bfloat16* sBl = (__nv_bfloat16*)(sraw + 30720);
    float* stg = (float*)sraw;

    const int tid = threadIdx.x, lane = tid & 31, wid = tid >> 5;
    const int warp_m = wid & 1, warp_n = wid >> 1;     // 2 x 4 warps
    const int m0 = blockIdx.y * 128, n0 = blockIdx.x * 128;

    float acc[4][4][4] = {};
    for (int k0 = 0; k0 < DD; k0 += 32) {
        load_split32(sAh, sAl, A + (size_t)m0 * DD + k0, DD, 128, tid);
        load_split32(sBh, sBl, W + (size_t)n0 * DD + k0, DD, 128, tid);
        __syncthreads();
        block_mma_k32<4, 4>(sAh, sAl, sBh, sBl, warp_m * 64, warp_n * 32, lane, acc);
        __syncthreads();
    }

    const int b = m0 >> 11, l0 = m0 & (LL - 1);
    for (int g = 0; g < 4; g++) {
        if (warp_n == g) stage_group<4, 4>(stg, warp_m, lane, acc, 1.0f);
        __syncthreads();
        const int n_base = n0 + g * 32;
        if (MODE == 1) {
            const int h = n_base >> 6, cc = n_base & 63;
            float* dst = out + ((size_t)(b * HH + h) * DKK + cc) * LL + l0;
            for (int u = tid; u < 1024; u += 256) {
                const int c = u >> 5, l4 = (u & 31) << 2;
                const float bv = bias[n_base + c];
                float4 v;
                v.x = stg[(size_t)(l4 + 0) * 33 + c] + bv;
                v.y = stg[(size_t)(l4 + 1) * 33 + c] + bv;
                v.z = stg[(size_t)(l4 + 2) * 33 + c] + bv;
                v.w = stg[(size_t)(l4 + 3) * 33 + c] + bv;
                *(float4*)(dst + (size_t)c * LL + l4) = v;
            }
        } else {
            for (int u = tid; u < 1024; u += 256) {
                const int r = u >> 3, c4 = (u & 7) << 2;
                float4 v;
                v.x = stg[(size_t)r * 33 + c4 + 0] + bias[n_base + c4 + 0];
                v.y = stg[(size_t)r * 33 + c4 + 1] + bias[n_base + c4 + 1];
                v.z = stg[(size_t)r * 33 + c4 + 2] + bias[n_base + c4 + 2];
                v.w = stg[(size_t)r * 33 + c4 + 3] + bias[n_base + c4 + 3];
                if (MODE == 0) {
                    const int h = n_base >> 6, cc = (n_base & 63) + c4;
                    *(float4*)(out + ((size_t)(b * HH + h) * LL + l0 + r) * DKK + cc) = v;
                } else {
                    *(float4*)(out + (size_t)(m0 + r) * DD + n_base + c4) = v;
                }
            }
        }
        __syncthreads();
    }
}

// ================= scores: S = Q K^T / 8 (causal tiles only) =================
__global__ void __launch_bounds__(256)
scores_mma(const float* __restrict__ q, const float* __restrict__ k,
           float* __restrict__ attn) {
    const int kt = blockIdx.x, qt = blockIdx.y, bhid = blockIdx.z;
    if (kt > qt) return;
    __shared__ __align__(16) char sraw[40960];
    __nv_bfloat16* sAh = (__nv_bfloat16*)(sraw);
    __nv_bfloat16* sAl = (__nv_bfloat16*)(sraw + 10240);
    __nv_bfloat16* sBh = (__nv_bfloat16*)(sraw + 20480);
    __nv_bfloat16* sBl = (__nv_bfloat16*)(sraw + 30720);
    float* stg = (float*)sraw;

    const int tid = threadIdx.x, lane = tid & 31, wid = tid >> 5;
    const int warp_m = wid & 1, warp_n = wid >> 1;
    const int q0 = qt * 128, kk0 = kt * 128;

    float acc[4][4][4] = {};
    #pragma unroll
    for (int k0 = 0; k0 < DKK; k0 += 32) {
        load_split32(sAh, sAl, q + ((size_t)bhid * LL + q0) * DKK + k0, DKK, 128, tid);
        load_split32(sBh, sBl, k + ((size_t)bhid * LL + kk0) * DKK + k0, DKK, 128, tid);
        __syncthreads();
        block_mma_k32<4, 4>(sAh, sAl, sBh, sBl, warp_m * 64, warp_n * 32, lane, acc);
        __syncthreads();
    }

    for (int g = 0; g < 4; g++) {
        if (warp_n == g) stage_group<4, 4>(stg, warp_m, lane, acc, 0.125f);
        __syncthreads();
        for (int u = tid; u < 1024; u += 256) {
            const int r = u >> 3, c4 = (u & 7) << 2;
            float4 v = make_float4(stg[(size_t)r * 33 + c4 + 0], stg[(size_t)r * 33 + c4 + 1],
                                   stg[(size_t)r * 33 + c4 + 2], stg[(size_t)r * 33 + c4 + 3]);
            *(float4*)(attn + ((size_t)bhid * LL + q0 + r) * LL + kk0 + g * 32 + c4) = v;
        }
        __syncthreads();
    }
}

// ================= O = P @ V (causal k-range) =================
__global__ void __launch_bounds__(256)
av_mma(const float* __restrict__ attn, const float* __restrict__ vt,
       float* __restrict__ oc) {
    const int qt = blockIdx.x, bhid = blockIdx.y;
    const int b = bhid >> 4, h = bhid & 15;
    __shared__ __align__(16) char sraw[40960];
    __nv_bfloat16* sAh = (__nv_bfloat16*)(sraw);
    __nv_bfloat16* sAl = (__nv_bfloat16*)(sraw + 10240);
    __nv_bfloat16* sBh = (__nv_bfloat16*)(sraw + 20480);
    __nv_bfloat16* sBl = (__nv_bfloat16*)(sraw + 30720);
    float* stg = (float*)sraw;

    const int tid = threadIdx.x, lane = tid & 31, wid = tid >> 5;
    const int warp_m = wid & 3, warp_n = wid >> 2;     // 4 x 2 warps
    const int q0 = qt * 128;

    const float* Pb = attn + ((size_t)bhid * LL + q0) * LL;
    const float* Vb = vt + (size_t)bhid * DKK * LL;

    float acc[2][4][4] = {};
    const int kend = (qt + 1) * 128;
    for (int k0 = 0; k0 < kend; k0 += 32) {
        load_split32(sAh, sAl, Pb + k0, LL, 128, tid);
        load_split32(sBh, sBl, Vb + k0, LL, DKK, tid);
        __syncthreads();
        block_mma_k32<2, 4>(sAh, sAl, sBh, sBl, warp_m * 32, warp_n * 32, lane, acc);
        __syncthreads();
    }

    for (int g = 0; g < 2; g++) {
        if (warp_n == g) stage_group<2, 4>(stg, warp_m, lane, acc, 1.0f);
        __syncthreads();
        for (int u = tid; u < 1024; u += 256) {
            const int r = u >> 3, c4 = (u & 7) << 2;
            float4 v = make_float4(stg[(size_t)r * 33 + c4 + 0], stg[(size_t)r * 33 + c4 + 1],
                                   stg[(size_t)r * 33 + c4 + 2], stg[(size_t)r * 33 + c4 + 3]);
            *(float4*)(oc + (size_t)(b * LL + q0 + r) * DD + h * DKK + g * 32 + c4) = v;
        }
        __syncthreads();
    }
}

// ================= row softmax (causal) =================
__global__ void softmax_kernel(float* __restrict__ attn) {
    const int row = blockIdx.x, bh = blockIdx.y;
    float* p = attn + ((size_t)bh * LL + row) * LL;
    const int valid = row + 1;
    const int tid = threadIdx.x;

    __shared__ float sred[8];

    float4 v[2];
    float m = -3.4e38f;
    #pragma unroll
    for (int i = 0; i < 2; i++) {
        const int j = (tid + i * 256) * 4;
        v[i] = *(const float4*)(p + j);
        if (j + 0 < valid) m = fmaxf(m, v[i].x);
        if (j + 1 < valid) m = fmaxf(m, v[i].y);
        if (j + 2 < valid) m = fmaxf(m, v[i].z);
        if (j + 3 < valid) m = fmaxf(m, v[i].w);
    }
    #pragma unroll
    for (int o = 16; o > 0; o >>= 1) m = fmaxf(m, __shfl_xor_sync(0xffffffff, m, o));
    if ((tid & 31) == 0) sred[tid >> 5] = m;
    __syncthreads();
    m = sred[0];
    #pragma unroll
    for (int w = 1; w < 8; w++) m = fmaxf(m, sred[w]);

    float sum = 0.0f;
    #pragma unroll
    for (int i = 0; i < 2; i++) {
        const int j = (tid + i * 256) * 4;
        v[i].x = (j + 0 < valid) ? __expf(v[i].x - m) : 0.0f;
        v[i].y = (j + 1 < valid) ? __expf(v[i].y - m) : 0.0f;
        v[i].z = (j + 2 < valid) ? __expf(v[i].z - m) : 0.0f;
        v[i].w = (j + 3 < valid) ? __expf(v[i].w - m) : 0.0f;
        sum += v[i].x + v[i].y + v[i].z + v[i].w;
    }
    __syncthreads();
    #pragma unroll
    for (int o = 16; o > 0; o >>= 1) sum += __shfl_xor_sync(0xffffffff, sum, o);
    if ((tid & 31) == 0) sred[tid >> 5] = sum;
    __syncthreads();
    sum = 0.0f;
    #pragma unroll
    for (int w = 0; w < 8; w++) sum += sred[w];
    const float inv = 1.0f / sum;

    #pragma unroll
    for (int i = 0; i < 2; i++) {
        const int j = (tid + i * 256) * 4;
        float4 o4;
        o4.x = v[i].x * inv; o4.y = v[i].y * inv;
        o4.z = v[i].z * inv; o4.w = v[i].w * inv;
        *(float4*)(p + j) = o4;
    }
}

// ---------------- launch ----------------
extern "C" void kernel_launch(void* const* d_in, const int* in_sizes, int n_in,
                              void* d_out, int out_size) {
    const float* x  = (const float*)d_in[0];
    const float* Wq = (const float*)d_in[2];
    const float* bq = (const float*)d_in[3];
    const float* Wk = (const float*)d_in[4];
    const float* bk = (const float*)d_in[5];
    const float* Wv = (const float*)d_in[6];
    const float* bv = (const float*)d_in[7];
    const float* Wo = (const float*)d_in[8];
    const float* bo = (const float*)d_in[9];
    float* out = (float*)d_out;

    const size_t out_elems  = (size_t)BB * LL * DD;
    const size_t attn_elems = (size_t)BH * LL * LL;

    float *q, *k, *vt, *oc, *attn;
    cudaGetSymbolAddress((void**)&q,  g_q);
    cudaGetSymbolAddress((void**)&k,  g_k);
    cudaGetSymbolAddress((void**)&vt, g_vt);
    cudaGetSymbolAddress((void**)&oc, g_oc);
    if ((size_t)out_size >= out_elems + attn_elems) {
        attn = out + out_elems;
    } else {
        cudaGetSymbolAddress((void**)&attn, g_attn_scratch);
    }

    dim3 projGrid(DD / 128, MROWS / 128);      // (8, 64)
    gemm_proj<0><<<projGrid, 256>>>(x, Wq, bq, q);
    gemm_proj<0><<<projGrid, 256>>>(x, Wk, bk, k);
    gemm_proj<1><<<projGrid, 256>>>(x, Wv, bv, vt);

    dim3 scoreGrid(LL / 128, LL / 128, BH);    // (16, 16, 64)
    scores_mma<<<scoreGrid, 256>>>(q, k, attn);

    dim3 smGrid(LL, BH);
    softmax_kernel<<<smGrid, 256>>>(attn);

    dim3 avGrid(LL / 128, BH);                 // (16, 64)
    av_mma<<<avGrid, 256>>>(attn, vt, oc);

    gemm_proj<2><<<projGrid, 256>>>(oc, Wo, bo, out);
}

// round 4
// speedup vs baseline: 2.6017x; 1.6078x over previous
#include <cuda_runtime.h>
#include <cuda_bf16.h>
#include <cstdint>
#include <math.h>

#define BB 4
#define LL 2048
#define DD 1024
#define HH 16
#define DKK 64
#define BH (BB*HH)        // 64
#define MROWS (BB*LL)     // 8192

#define SPAD 40           // smem row stride (bf16) for K=32 chunks
#define SPAD2 72          // smem row stride (bf16) for K=64 single-stage (scores)

// pipelined-stage smem layout (proj / av): per stage
#define ST_AH 0
#define ST_AL 10240       // 128*40*2
#define ST_BH 20480
#define ST_BL 25600       // 64*40*2
#define STAGE_BYTES 30720
#define PIPE_SMEM (2*STAGE_BYTES)      // 61440

// scores smem layout
#define SC_AH 0
#define SC_AL 18432       // 128*72*2
#define SC_BH 36864
#define SC_BL 55296
#define SC_SMEM 73728

// ---------------- device scratch (allocation-free) ----------------
__device__ float g_q[(size_t)BH * LL * DKK];     // [bh][l][dk]
__device__ float g_k[(size_t)BH * LL * DKK];
__device__ float g_vt[(size_t)BH * DKK * LL];    // [bh][dk][l]  (V transposed)
__device__ float g_oc[(size_t)MROWS * DD];       // concat attention output
__device__ float g_attn_scratch[(size_t)BH * LL * LL]; // fallback

// ---------------- mma helpers ----------------
__device__ __forceinline__ uint32_t s32(const void* p) {
    return (uint32_t)__cvta_generic_to_shared(p);
}

#define LDSM_X4(R, a)                                                          \
    asm volatile("ldmatrix.sync.aligned.m8n8.x4.shared.b16 {%0,%1,%2,%3}, [%4];" \
        : "=r"((R)[0]), "=r"((R)[1]), "=r"((R)[2]), "=r"((R)[3]) : "r"(a))
#define LDSM_X2(R, a)                                                          \
    asm volatile("ldmatrix.sync.aligned.m8n8.x2.shared.b16 {%0,%1}, [%2];"     \
        : "=r"((R)[0]), "=r"((R)[1]) : "r"(a))

__device__ __forceinline__ void mma_bf16(float* c, const uint32_t* a, const uint32_t* b) {
    asm volatile(
        "mma.sync.aligned.m16n8k16.row.col.f32.bf16.bf16.f32 "
        "{%0,%1,%2,%3}, {%4,%5,%6,%7}, {%8,%9}, {%0,%1,%2,%3};"
        : "+f"(c[0]), "+f"(c[1]), "+f"(c[2]), "+f"(c[3])
        : "r"(a[0]), "r"(a[1]), "r"(a[2]), "r"(a[3]), "r"(b[0]), "r"(b[1]));
}

__device__ __forceinline__ void cvt_split(const float4& v, uint2& hv, uint2& lv) {
    __nv_bfloat16 h0 = __float2bfloat16(v.x), h1 = __float2bfloat16(v.y);
    __nv_bfloat16 h2 = __float2bfloat16(v.z), h3 = __float2bfloat16(v.w);
    __nv_bfloat16 l0 = __float2bfloat16(v.x - __bfloat162float(h0));
    __nv_bfloat16 l1 = __float2bfloat16(v.y - __bfloat162float(h1));
    __nv_bfloat16 l2 = __float2bfloat16(v.z - __bfloat162float(h2));
    __nv_bfloat16 l3 = __float2bfloat16(v.w - __bfloat162float(h3));
    hv.x = ((uint32_t)__bfloat16_as_ushort(h1) << 16) | __bfloat16_as_ushort(h0);
    hv.y = ((uint32_t)__bfloat16_as_ushort(h3) << 16) | __bfloat16_as_ushort(h2);
    lv.x = ((uint32_t)__bfloat16_as_ushort(l1) << 16) | __bfloat16_as_ushort(l0);
    lv.y = ((uint32_t)__bfloat16_as_ushort(l3) << 16) | __bfloat16_as_ushort(l2);
}

// ---- pipelined chunk helpers: [rows x 32] fp32 (row stride ld) ----
template <int N4>
__device__ __forceinline__ void ldg_chunk(float4 (&r)[N4], const float* __restrict__ g,
                                          int ld, int tid) {
    #pragma unroll
    for (int i = 0; i < N4; i++) {
        const int u = tid + i * 256;
        const int row = u >> 3, c4 = (u & 7) << 2;
        r[i] = *(const float4*)(g + (size_t)row * ld + c4);
    }
}
template <int N4>
__device__ __forceinline__ void sts_chunk(const float4 (&v)[N4], __nv_bfloat16* shi,
                                          __nv_bfloat16* slo, int tid) {
    #pragma unroll
    for (int i = 0; i < N4; i++) {
        const int u = tid + i * 256;
        const int row = u >> 3, c4 = (u & 7) << 2;
        uint2 hv, lv; cvt_split(v[i], hv, lv);
        *(uint2*)(shi + row * SPAD + c4) = hv;
        *(uint2*)(slo + row * SPAD + c4) = lv;
    }
}

// scores single-stage loader: [128 x 64] fp32 -> hi/lo bf16 (stride SPAD2)
__device__ __forceinline__ void load_split64(__nv_bfloat16* shi, __nv_bfloat16* slo,
                                             const float* __restrict__ g, int ld, int tid) {
    #pragma unroll
    for (int i = 0; i < 8; i++) {
        const int u = tid + i * 256;
        const int r = u >> 4, c4 = (u & 15) << 2;
        float4 v = *(const float4*)(g + (size_t)r * ld + c4);
        uint2 hv, lv; cvt_split(v, hv, lv);
        *(uint2*)(shi + r * SPAD2 + c4) = hv;
        *(uint2*)(slo + r * SPAD2 + c4) = lv;
    }
}

// One K-chunk of split-bf16 3-pass MMA (AhBh + AhBl + AlBh).
template <int MT, int NT, int STRIDE, int KC>
__device__ __forceinline__ void block_mma(
    const __nv_bfloat16* sAh, const __nv_bfloat16* sAl,
    const __nv_bfloat16* sBh, const __nv_bfloat16* sBl,
    int a_row0, int b_row0, int lane, float (&acc)[MT][NT][4]) {
    #pragma unroll
    for (int kb = 0; kb < KC; kb += 16) {
        uint32_t ah[MT][4], al[MT][4], bh[NT][2], bl[NT][2];
        const int ar = a_row0 + (lane & 15);
        const int ac = kb + ((lane >> 4) << 3);
        #pragma unroll
        for (int i = 0; i < MT; i++) {
            LDSM_X4(ah[i], s32(sAh + (ar + i * 16) * STRIDE + ac));
            LDSM_X4(al[i], s32(sAl + (ar + i * 16) * STRIDE + ac));
        }
        const int br = b_row0 + (lane & 7);
        const int bc = kb + (((lane >> 3) & 1) << 3);
        #pragma unroll
        for (int j = 0; j < NT; j++) {
            LDSM_X2(bh[j], s32(sBh + (br + j * 8) * STRIDE + bc));
            LDSM_X2(bl[j], s32(sBl + (br + j * 8) * STRIDE + bc));
        }
        #pragma unroll
        for (int i = 0; i < MT; i++)
            #pragma unroll
            for (int j = 0; j < NT; j++) {
                mma_bf16(acc[i][j], ah[i], bh[j]);
                mma_bf16(acc[i][j], ah[i], bl[j]);
                mma_bf16(acc[i][j], al[i], bh[j]);
            }
    }
}

// Stage a 32-col accumulator group into fp32 smem [128][33].
template <int MT, int NT>
__device__ __forceinline__ void stage_group(float* stg, int warp_m, int col_base, int lane,
                                            float (&acc)[MT][NT][4], float scale) {
    const int r0 = warp_m * MT * 16 + (lane >> 2);
    const int c0 = (lane & 3) * 2;
    #pragma unroll
    for (int i = 0; i < MT; i++)
        #pragma unroll
        for (int j = 0; j < NT; j++) {
            float* p = stg + (size_t)(r0 + i * 16) * 33 + col_base + j * 8 + c0;
            p[0] = acc[i][j][0] * scale;
            p[1] = acc[i][j][1] * scale;
            p[8 * 33 + 0] = acc[i][j][2] * scale;
            p[8 * 33 + 1] = acc[i][j][3] * scale;
        }
}

// ================= projection GEMM: C = A @ W^T + bias (tile 128x64, pipelined) ====
// MODE 0: headed   out[((b*16+h)*2048 + l)*64 + c]
// MODE 1: V^T      out[((b*16+h)*64 + c)*2048 + l]
// MODE 2: flat     out[m*1024 + n]
template <int MODE>
__global__ void __launch_bounds__(256, 2)
gemm_proj(const float* __restrict__ A, const float* __restrict__ W,
          const float* __restrict__ bias, float* __restrict__ out) {
    extern __shared__ char sm[];
    const int tid = threadIdx.x, lane = tid & 31, wid = tid >> 5;
    const int warp_m = wid & 1, warp_n = wid >> 1;     // 2 x 4; warp tile 64x16
    const int m0 = blockIdx.y * 128, n0 = blockIdx.x * 64;

    const float* Ab = A + (size_t)m0 * DD;
    const float* Wb = W + (size_t)n0 * DD;

    float acc[4][2][4] = {};
    float4 ra[4], rb[2];

    // prologue: chunk0 -> stage0, prefetch chunk1
    ldg_chunk<4>(ra, Ab, DD, tid);
    ldg_chunk<2>(rb, Wb, DD, tid);
    {
        char* s0 = sm;
        sts_chunk<4>(ra, (__nv_bfloat16*)(s0 + ST_AH), (__nv_bfloat16*)(s0 + ST_AL), tid);
        sts_chunk<2>(rb, (__nv_bfloat16*)(s0 + ST_BH), (__nv_bfloat16*)(s0 + ST_BL), tid);
    }
    ldg_chunk<4>(ra, Ab + 32, DD, tid);
    ldg_chunk<2>(rb, Wb + 32, DD, tid);
    __syncthreads();

    const int NK = DD / 32;   // 32
    for (int k = 0; k < NK; k++) {
        char* cur = sm + (k & 1) * STAGE_BYTES;
        block_mma<4, 2, SPAD, 32>((__nv_bfloat16*)(cur + ST_AH), (__nv_bfloat16*)(cur + ST_AL),
                                  (__nv_bfloat16*)(cur + ST_BH), (__nv_bfloat16*)(cur + ST_BL),
                                  warp_m * 64, warp_n * 16, lane, acc);
        if (k + 1 < NK) {
            char* nxt = sm + ((k + 1) & 1) * STAGE_BYTES;
            sts_chunk<4>(ra, (__nv_bfloat16*)(nxt + ST_AH), (__nv_bfloat16*)(nxt + ST_AL), tid);
            sts_chunk<2>(rb, (__nv_bfloat16*)(nxt + ST_BH), (__nv_bfloat16*)(nxt + ST_BL), tid);
        }
        if (k + 2 < NK) {
            ldg_chunk<4>(ra, Ab + (k + 2) * 32, DD, tid);
            ldg_chunk<2>(rb, Wb + (k + 2) * 32, DD, tid);
        }
        __syncthreads();
    }

    // epilogue: 2 groups of 32 cols
    float* stg = (float*)sm;
    const int b = m0 >> 11, l0 = m0 & (LL - 1);
    for (int g = 0; g < 2; g++) {
        if ((warp_n >> 1) == g)
            stage_group<4, 2>(stg, warp_m, (warp_n & 1) * 16, lane, acc, 1.0f);
        __syncthreads();
        const int n_base = n0 + g * 32;
        if (MODE == 1) {
            const int h = n_base >> 6, cc = n_base & 63;
            float* dst = out + ((size_t)(b * HH + h) * DKK + cc) * LL + l0;
            for (int u = tid; u < 1024; u += 256) {
                const int c = u >> 5, l4 = (u & 31) << 2;
                const float bv = bias[n_base + c];
                float4 v;
                v.x = stg[(size_t)(l4 + 0) * 33 + c] + bv;
                v.y = stg[(size_t)(l4 + 1) * 33 + c] + bv;
                v.z = stg[(size_t)(l4 + 2) * 33 + c] + bv;
                v.w = stg[(size_t)(l4 + 3) * 33 + c] + bv;
                *(float4*)(dst + (size_t)c * LL + l4) = v;
            }
        } else {
            for (int u = tid; u < 1024; u += 256) {
                const int r = u >> 3, c4 = (u & 7) << 2;
                float4 v;
                v.x = stg[(size_t)r * 33 + c4 + 0] + bias[n_base + c4 + 0];
                v.y = stg[(size_t)r * 33 + c4 + 1] + bias[n_base + c4 + 1];
                v.z = stg[(size_t)r * 33 + c4 + 2] + bias[n_base + c4 + 2];
                v.w = stg[(size_t)r * 33 + c4 + 3] + bias[n_base + c4 + 3];
                if (MODE == 0) {
                    const int h = n_base >> 6, cc = (n_base & 63) + c4;
                    *(float4*)(out + ((size_t)(b * HH + h) * LL + l0 + r) * DKK + cc) = v;
                } else {
                    *(float4*)(out + (size_t)(m0 + r) * DD + n_base + c4) = v;
                }
            }
        }
        __syncthreads();
    }
}

// ================= scores: S = Q K^T / 8 (single K=64 stage) =================
__global__ void __launch_bounds__(256, 2)
scores_mma(const float* __restrict__ q, const float* __restrict__ k,
           float* __restrict__ attn) {
    const int kt = blockIdx.x, qt = blockIdx.y, bhid = blockIdx.z;
    if (kt > qt) return;
    extern __shared__ char sm[];
    const int tid = threadIdx.x, lane = tid & 31, wid = tid >> 5;
    const int warp_m = wid & 1, warp_n = wid >> 1;     // 2 x 4; warp tile 64x32
    const int q0 = qt * 128, kk0 = kt * 128;

    load_split64((__nv_bfloat16*)(sm + SC_AH), (__nv_bfloat16*)(sm + SC_AL),
                 q + ((size_t)bhid * LL + q0) * DKK, DKK, tid);
    load_split64((__nv_bfloat16*)(sm + SC_BH), (__nv_bfloat16*)(sm + SC_BL),
                 k + ((size_t)bhid * LL + kk0) * DKK, DKK, tid);
    __syncthreads();

    float acc[4][4][4] = {};
    block_mma<4, 4, SPAD2, 64>((__nv_bfloat16*)(sm + SC_AH), (__nv_bfloat16*)(sm + SC_AL),
                               (__nv_bfloat16*)(sm + SC_BH), (__nv_bfloat16*)(sm + SC_BL),
                               warp_m * 64, warp_n * 32, lane, acc);
    __syncthreads();

    float* stg = (float*)sm;
    for (int g = 0; g < 4; g++) {
        if (warp_n == g) stage_group<4, 4>(stg, warp_m, 0, lane, acc, 0.125f);
        __syncthreads();
        for (int u = tid; u < 1024; u += 256) {
            const int r = u >> 3, c4 = (u & 7) << 2;
            float4 v = make_float4(stg[(size_t)r * 33 + c4 + 0], stg[(size_t)r * 33 + c4 + 1],
                                   stg[(size_t)r * 33 + c4 + 2], stg[(size_t)r * 33 + c4 + 3]);
            *(float4*)(attn + ((size_t)bhid * LL + q0 + r) * LL + kk0 + g * 32 + c4) = v;
        }
        __syncthreads();
    }
}

// ================= O = P @ V (causal k-range, pipelined) =================
__global__ void __launch_bounds__(256, 2)
av_mma(const float* __restrict__ attn, const float* __restrict__ vt,
       float* __restrict__ oc) {
    const int qt = blockIdx.x, bhid = blockIdx.y;
    const int b = bhid >> 4, h = bhid & 15;
    extern __shared__ char sm[];
    const int tid = threadIdx.x, lane = tid & 31, wid = tid >> 5;
    const int warp_m = wid & 1, warp_n = wid >> 1;     // 2 x 4; warp tile 64x16
    const int q0 = qt * 128;

    const float* Pb = attn + ((size_t)bhid * LL + q0) * LL;
    const float* Vb = vt + (size_t)bhid * DKK * LL;

    float acc[4][2][4] = {};
    float4 ra[4], rb[2];

    const int NK = (qt + 1) * 4;   // K chunks of 32; >= 4

    ldg_chunk<4>(ra, Pb, LL, tid);
    ldg_chunk<2>(rb, Vb, LL, tid);
    {
        char* s0 = sm;
        sts_chunk<4>(ra, (__nv_bfloat16*)(s0 + ST_AH), (__nv_bfloat16*)(s0 + ST_AL), tid);
        sts_chunk<2>(rb, (__nv_bfloat16*)(s0 + ST_BH), (__nv_bfloat16*)(s0 + ST_BL), tid);
    }
    ldg_chunk<4>(ra, Pb + 32, LL, tid);
    ldg_chunk<2>(rb, Vb + 32, LL, tid);
    __syncthreads();

    for (int k = 0; k < NK; k++) {
        char* cur = sm + (k & 1) * STAGE_BYTES;
        block_mma<4, 2, SPAD, 32>((__nv_bfloat16*)(cur + ST_AH), (__nv_bfloat16*)(cur + ST_AL),
                                  (__nv_bfloat16*)(cur + ST_BH), (__nv_bfloat16*)(cur + ST_BL),
                                  warp_m * 64, warp_n * 16, lane, acc);
        if (k + 1 < NK) {
            char* nxt = sm + ((k + 1) & 1) * STAGE_BYTES;
            sts_chunk<4>(ra, (__nv_bfloat16*)(nxt + ST_AH), (__nv_bfloat16*)(nxt + ST_AL), tid);
            sts_chunk<2>(rb, (__nv_bfloat16*)(nxt + ST_BH), (__nv_bfloat16*)(nxt + ST_BL), tid);
        }
        if (k + 2 < NK) {
            ldg_chunk<4>(ra, Pb + (k + 2) * 32, LL, tid);
            ldg_chunk<2>(rb, Vb + (k + 2) * 32, LL, tid);
        }
        __syncthreads();
    }

    float* stg = (float*)sm;
    for (int g = 0; g < 2; g++) {
        if ((warp_n >> 1) == g)
            stage_group<4, 2>(stg, warp_m, (warp_n & 1) * 16, lane, acc, 1.0f);
        __syncthreads();
        for (int u = tid; u < 1024; u += 256) {
            const int r = u >> 3, c4 = (u & 7) << 2;
            float4 v = make_float4(stg[(size_t)r * 33 + c4 + 0], stg[(size_t)r * 33 + c4 + 1],
                                   stg[(size_t)r * 33 + c4 + 2], stg[(size_t)r * 33 + c4 + 3]);
            *(float4*)(oc + (size_t)(b * LL + q0 + r) * DD + h * DKK + g * 32 + c4) = v;
        }
        __syncthreads();
    }
}

// ================= row softmax (causal) =================
__global__ void softmax_kernel(float* __restrict__ attn) {
    const int row = blockIdx.x, bh = blockIdx.y;
    float* p = attn + ((size_t)bh * LL + row) * LL;
    const int valid = row + 1;
    const int tid = threadIdx.x;

    __shared__ float sred[8];

    float4 v[2];
    float m = -3.4e38f;
    #pragma unroll
    for (int i = 0; i < 2; i++) {
        const int j = (tid + i * 256) * 4;
        v[i] = *(const float4*)(p + j);
        if (j + 0 < valid) m = fmaxf(m, v[i].x);
        if (j + 1 < valid) m = fmaxf(m, v[i].y);
        if (j + 2 < valid) m = fmaxf(m, v[i].z);
        if (j + 3 < valid) m = fmaxf(m, v[i].w);
    }
    #pragma unroll
    for (int o = 16; o > 0; o >>= 1) m = fmaxf(m, __shfl_xor_sync(0xffffffff, m, o));
    if ((tid & 31) == 0) sred[tid >> 5] = m;
    __syncthreads();
    m = sred[0];
    #pragma unroll
    for (int w = 1; w < 8; w++) m = fmaxf(m, sred[w]);

    float sum = 0.0f;
    #pragma unroll
    for (int i = 0; i < 2; i++) {
        const int j = (tid + i * 256) * 4;
        v[i].x = (j + 0 < valid) ? __expf(v[i].x - m) : 0.0f;
        v[i].y = (j + 1 < valid) ? __expf(v[i].y - m) : 0.0f;
        v[i].z = (j + 2 < valid) ? __expf(v[i].z - m) : 0.0f;
        v[i].w = (j + 3 < valid) ? __expf(v[i].w - m) : 0.0f;
        sum += v[i].x + v[i].y + v[i].z + v[i].w;
    }
    __syncthreads();
    #pragma unroll
    for (int o = 16; o > 0; o >>= 1) sum += __shfl_xor_sync(0xffffffff, sum, o);
    if ((tid & 31) == 0) sred[tid >> 5] = sum;
    __syncthreads();
    sum = 0.0f;
    #pragma unroll
    for (int w = 0; w < 8; w++) sum += sred[w];
    const float inv = 1.0f / sum;

    #pragma unroll
    for (int i = 0; i < 2; i++) {
        const int j = (tid + i * 256) * 4;
        float4 o4;
        o4.x = v[i].x * inv; o4.y = v[i].y * inv;
        o4.z = v[i].z * inv; o4.w = v[i].w * inv;
        *(float4*)(p + j) = o4;
    }
}

// ---------------- launch ----------------
extern "C" void kernel_launch(void* const* d_in, const int* in_sizes, int n_in,
                              void* d_out, int out_size) {
    const float* x  = (const float*)d_in[0];
    const float* Wq = (const float*)d_in[2];
    const float* bq = (const float*)d_in[3];
    const float* Wk = (const float*)d_in[4];
    const float* bk = (const float*)d_in[5];
    const float* Wv = (const float*)d_in[6];
    const float* bv = (const float*)d_in[7];
    const float* Wo = (const float*)d_in[8];
    const float* bo = (const float*)d_in[9];
    float* out = (float*)d_out;

    const size_t out_elems  = (size_t)BB * LL * DD;
    const size_t attn_elems = (size_t)BH * LL * LL;

    float *q, *k, *vt, *oc, *attn;
    cudaGetSymbolAddress((void**)&q,  g_q);
    cudaGetSymbolAddress((void**)&k,  g_k);
    cudaGetSymbolAddress((void**)&vt, g_vt);
    cudaGetSymbolAddress((void**)&oc, g_oc);
    if ((size_t)out_size >= out_elems + attn_elems) {
        attn = out + out_elems;
    } else {
        cudaGetSymbolAddress((void**)&attn, g_attn_scratch);
    }

    cudaFuncSetAttribute(gemm_proj<0>, cudaFuncAttributeMaxDynamicSharedMemorySize, PIPE_SMEM);
    cudaFuncSetAttribute(gemm_proj<1>, cudaFuncAttributeMaxDynamicSharedMemorySize, PIPE_SMEM);
    cudaFuncSetAttribute(gemm_proj<2>, cudaFuncAttributeMaxDynamicSharedMemorySize, PIPE_SMEM);
    cudaFuncSetAttribute(scores_mma,   cudaFuncAttributeMaxDynamicSharedMemorySize, SC_SMEM);
    cudaFuncSetAttribute(av_mma,       cudaFuncAttributeMaxDynamicSharedMemorySize, PIPE_SMEM);

    dim3 projGrid(DD / 64, MROWS / 128);       // (16, 64)
    gemm_proj<0><<<projGrid, 256, PIPE_SMEM>>>(x, Wq, bq, q);
    gemm_proj<0><<<projGrid, 256, PIPE_SMEM>>>(x, Wk, bk, k);
    gemm_proj<1><<<projGrid, 256, PIPE_SMEM>>>(x, Wv, bv, vt);

    dim3 scoreGrid(LL / 128, LL / 128, BH);    // (16, 16, 64)
    scores_mma<<<scoreGrid, 256, SC_SMEM>>>(q, k, attn);

    dim3 smGrid(LL, BH);
    softmax_kernel<<<smGrid, 256>>>(attn);

    dim3 avGrid(LL / 128, BH);                 // (16, 64)
    av_mma<<<avGrid, 256, PIPE_SMEM>>>(attn, vt, oc);

    gemm_proj<2><<<projGrid, 256, PIPE_SMEM>>>(oc, Wo, bo, out);
}

// round 5
// speedup vs baseline: 2.6733x; 1.0275x over previous
#include <cuda_runtime.h>
#include <cuda_bf16.h>
#include <cstdint>
#include <math.h>

#define BB 4
#define LL 2048
#define DD 1024
#define HH 16
#define DKK 64
#define BH (BB*HH)        // 64
#define MROWS (BB*LL)     // 8192

#define SPAD 40           // smem row stride (bf16) for K=32 chunks
#define SPAD2 72          // smem row stride (bf16) for K=64 tiles (scores)

// pipelined-stage smem layout (proj / av): per stage
#define ST_AH 0
#define ST_AL 10240       // 128*40*2
#define ST_BH 20480
#define ST_BL 25600       // 64*40*2
#define STAGE_BYTES 30720
#define PIPE_SMEM (2*STAGE_BYTES)      // 61440

// scores smem layout: Q hi/lo + K hi/lo + fp32 stage
#define SC_QH 0
#define SC_QL 18432       // 128*72*2
#define SC_KH 36864
#define SC_KL 55296
#define SC_STG 73728      // 128*33*4 = 16896
#define SC_SMEM 90624

// ---------------- device scratch (allocation-free) ----------------
__device__ float g_q[(size_t)BH * LL * DKK];     // [bh][l][dk]
__device__ float g_k[(size_t)BH * LL * DKK];
__device__ float g_vt[(size_t)BH * DKK * LL];    // [bh][dk][l]  (V transposed)
__device__ float g_oc[(size_t)MROWS * DD];       // concat attention output
__device__ float g_attn_scratch[(size_t)BH * LL * LL]; // fallback

// ---------------- mma helpers ----------------
__device__ __forceinline__ uint32_t s32(const void* p) {
    return (uint32_t)__cvta_generic_to_shared(p);
}

#define LDSM_X4(R, a)                                                          \
    asm volatile("ldmatrix.sync.aligned.m8n8.x4.shared.b16 {%0,%1,%2,%3}, [%4];" \
        : "=r"((R)[0]), "=r"((R)[1]), "=r"((R)[2]), "=r"((R)[3]) : "r"(a))
#define LDSM_X2(R, a)                                                          \
    asm volatile("ldmatrix.sync.aligned.m8n8.x2.shared.b16 {%0,%1}, [%2];"     \
        : "=r"((R)[0]), "=r"((R)[1]) : "r"(a))

__device__ __forceinline__ void mma_bf16(float* c, const uint32_t* a, const uint32_t* b) {
    asm volatile(
        "mma.sync.aligned.m16n8k16.row.col.f32.bf16.bf16.f32 "
        "{%0,%1,%2,%3}, {%4,%5,%6,%7}, {%8,%9}, {%0,%1,%2,%3};"
        : "+f"(c[0]), "+f"(c[1]), "+f"(c[2]), "+f"(c[3])
        : "r"(a[0]), "r"(a[1]), "r"(a[2]), "r"(a[3]), "r"(b[0]), "r"(b[1]));
}

__device__ __forceinline__ void cvt_split(const float4& v, uint2& hv, uint2& lv) {
    __nv_bfloat16 h0 = __float2bfloat16(v.x), h1 = __float2bfloat16(v.y);
    __nv_bfloat16 h2 = __float2bfloat16(v.z), h3 = __float2bfloat16(v.w);
    __nv_bfloat16 l0 = __float2bfloat16(v.x - __bfloat162float(h0));
    __nv_bfloat16 l1 = __float2bfloat16(v.y - __bfloat162float(h1));
    __nv_bfloat16 l2 = __float2bfloat16(v.z - __bfloat162float(h2));
    __nv_bfloat16 l3 = __float2bfloat16(v.w - __bfloat162float(h3));
    hv.x = ((uint32_t)__bfloat16_as_ushort(h1) << 16) | __bfloat16_as_ushort(h0);
    hv.y = ((uint32_t)__bfloat16_as_ushort(h3) << 16) | __bfloat16_as_ushort(h2);
    lv.x = ((uint32_t)__bfloat16_as_ushort(l1) << 16) | __bfloat16_as_ushort(l0);
    lv.y = ((uint32_t)__bfloat16_as_ushort(l3) << 16) | __bfloat16_as_ushort(l2);
}

// ---- pipelined chunk helpers: [rows x 32] fp32 (row stride ld) ----
template <int N4>
__device__ __forceinline__ void ldg_chunk(float4 (&r)[N4], const float* __restrict__ g,
                                          int ld, int tid) {
    #pragma unroll
    for (int i = 0; i < N4; i++) {
        const int u = tid + i * 256;
        const int row = u >> 3, c4 = (u & 7) << 2;
        r[i] = *(const float4*)(g + (size_t)row * ld + c4);
    }
}
template <int N4>
__device__ __forceinline__ void sts_chunk(const float4 (&v)[N4], __nv_bfloat16* shi,
                                          __nv_bfloat16* slo, int tid) {
    #pragma unroll
    for (int i = 0; i < N4; i++) {
        const int u = tid + i * 256;
        const int row = u >> 3, c4 = (u & 7) << 2;
        uint2 hv, lv; cvt_split(v[i], hv, lv);
        *(uint2*)(shi + row * SPAD + c4) = hv;
        *(uint2*)(slo + row * SPAD + c4) = lv;
    }
}

// [128 x 64] fp32 (row stride ld) -> split hi/lo bf16 smem (stride SPAD2)
__device__ __forceinline__ void load_split64(__nv_bfloat16* shi, __nv_bfloat16* slo,
                                             const float* __restrict__ g, int ld, int tid) {
    #pragma unroll
    for (int i = 0; i < 8; i++) {
        const int u = tid + i * 256;
        const int r = u >> 4, c4 = (u & 15) << 2;
        float4 v = *(const float4*)(g + (size_t)r * ld + c4);
        uint2 hv, lv; cvt_split(v, hv, lv);
        *(uint2*)(shi + r * SPAD2 + c4) = hv;
        *(uint2*)(slo + r * SPAD2 + c4) = lv;
    }
}

// One K-chunk of split-bf16 3-pass MMA (AhBh + AhBl + AlBh).
template <int MT, int NT, int STRIDE, int KC>
__device__ __forceinline__ void block_mma(
    const __nv_bfloat16* sAh, const __nv_bfloat16* sAl,
    const __nv_bfloat16* sBh, const __nv_bfloat16* sBl,
    int a_row0, int b_row0, int lane, float (&acc)[MT][NT][4]) {
    #pragma unroll
    for (int kb = 0; kb < KC; kb += 16) {
        uint32_t ah[MT][4], al[MT][4], bh[NT][2], bl[NT][2];
        const int ar = a_row0 + (lane & 15);
        const int ac = kb + ((lane >> 4) << 3);
        #pragma unroll
        for (int i = 0; i < MT; i++) {
            LDSM_X4(ah[i], s32(sAh + (ar + i * 16) * STRIDE + ac));
            LDSM_X4(al[i], s32(sAl + (ar + i * 16) * STRIDE + ac));
        }
        const int br = b_row0 + (lane & 7);
        const int bc = kb + (((lane >> 3) & 1) << 3);
        #pragma unroll
        for (int j = 0; j < NT; j++) {
            LDSM_X2(bh[j], s32(sBh + (br + j * 8) * STRIDE + bc));
            LDSM_X2(bl[j], s32(sBl + (br + j * 8) * STRIDE + bc));
        }
        #pragma unroll
        for (int i = 0; i < MT; i++)
            #pragma unroll
            for (int j = 0; j < NT; j++) {
                mma_bf16(acc[i][j], ah[i], bh[j]);
                mma_bf16(acc[i][j], ah[i], bl[j]);
                mma_bf16(acc[i][j], al[i], bh[j]);
            }
    }
}

// Stage a 32-col accumulator group into fp32 smem [128][33].
template <int MT, int NT>
__device__ __forceinline__ void stage_group(float* stg, int warp_m, int col_base, int lane,
                                            float (&acc)[MT][NT][4], float scale) {
    const int r0 = warp_m * MT * 16 + (lane >> 2);
    const int c0 = (lane & 3) * 2;
    #pragma unroll
    for (int i = 0; i < MT; i++)
        #pragma unroll
        for (int j = 0; j < NT; j++) {
            float* p = stg + (size_t)(r0 + i * 16) * 33 + col_base + j * 8 + c0;
            p[0] = acc[i][j][0] * scale;
            p[1] = acc[i][j][1] * scale;
            p[8 * 33 + 0] = acc[i][j][2] * scale;
            p[8 * 33 + 1] = acc[i][j][3] * scale;
        }
}

// ================= projection GEMM: C = A @ W^T + bias (tile 128x64, pipelined) ====
template <int MODE>
__global__ void __launch_bounds__(256, 2)
gemm_proj(const float* __restrict__ A, const float* __restrict__ W,
          const float* __restrict__ bias, float* __restrict__ out) {
    extern __shared__ char sm[];
    const int tid = threadIdx.x, lane = tid & 31, wid = tid >> 5;
    const int warp_m = wid & 1, warp_n = wid >> 1;     // 2 x 4; warp tile 64x16
    const int m0 = blockIdx.y * 128, n0 = blockIdx.x * 64;

    const float* Ab = A + (size_t)m0 * DD;
    const float* Wb = W + (size_t)n0 * DD;

    float acc[4][2][4] = {};
    float4 ra[4], rb[2];

    ldg_chunk<4>(ra, Ab, DD, tid);
    ldg_chunk<2>(rb, Wb, DD, tid);
    {
        char* s0 = sm;
        sts_chunk<4>(ra, (__nv_bfloat16*)(s0 + ST_AH), (__nv_bfloat16*)(s0 + ST_AL), tid);
        sts_chunk<2>(rb, (__nv_bfloat16*)(s0 + ST_BH), (__nv_bfloat16*)(s0 + ST_BL), tid);
    }
    ldg_chunk<4>(ra, Ab + 32, DD, tid);
    ldg_chunk<2>(rb, Wb + 32, DD, tid);
    __syncthreads();

    const int NK = DD / 32;   // 32
    for (int k = 0; k < NK; k++) {
        char* cur = sm + (k & 1) * STAGE_BYTES;
        block_mma<4, 2, SPAD, 32>((__nv_bfloat16*)(cur + ST_AH), (__nv_bfloat16*)(cur + ST_AL),
                                  (__nv_bfloat16*)(cur + ST_BH), (__nv_bfloat16*)(cur + ST_BL),
                                  warp_m * 64, warp_n * 16, lane, acc);
        if (k + 1 < NK) {
            char* nxt = sm + ((k + 1) & 1) * STAGE_BYTES;
            sts_chunk<4>(ra, (__nv_bfloat16*)(nxt + ST_AH), (__nv_bfloat16*)(nxt + ST_AL), tid);
            sts_chunk<2>(rb, (__nv_bfloat16*)(nxt + ST_BH), (__nv_bfloat16*)(nxt + ST_BL), tid);
        }
        if (k + 2 < NK) {
            ldg_chunk<4>(ra, Ab + (k + 2) * 32, DD, tid);
            ldg_chunk<2>(rb, Wb + (k + 2) * 32, DD, tid);
        }
        __syncthreads();
    }

    float* stg = (float*)sm;
    const int b = m0 >> 11, l0 = m0 & (LL - 1);
    for (int g = 0; g < 2; g++) {
        if ((warp_n >> 1) == g)
            stage_group<4, 2>(stg, warp_m, (warp_n & 1) * 16, lane, acc, 1.0f);
        __syncthreads();
        const int n_base = n0 + g * 32;
        if (MODE == 1) {
            const int h = n_base >> 6, cc = n_base & 63;
            float* dst = out + ((size_t)(b * HH + h) * DKK + cc) * LL + l0;
            for (int u = tid; u < 1024; u += 256) {
                const int c = u >> 5, l4 = (u & 31) << 2;
                const float bv = bias[n_base + c];
                float4 v;
                v.x = stg[(size_t)(l4 + 0) * 33 + c] + bv;
                v.y = stg[(size_t)(l4 + 1) * 33 + c] + bv;
                v.z = stg[(size_t)(l4 + 2) * 33 + c] + bv;
                v.w = stg[(size_t)(l4 + 3) * 33 + c] + bv;
                *(float4*)(dst + (size_t)c * LL + l4) = v;
            }
        } else {
            for (int u = tid; u < 1024; u += 256) {
                const int r = u >> 3, c4 = (u & 7) << 2;
                float4 v;
                v.x = stg[(size_t)r * 33 + c4 + 0] + bias[n_base + c4 + 0];
                v.y = stg[(size_t)r * 33 + c4 + 1] + bias[n_base + c4 + 1];
                v.z = stg[(size_t)r * 33 + c4 + 2] + bias[n_base + c4 + 2];
                v.w = stg[(size_t)r * 33 + c4 + 3] + bias[n_base + c4 + 3];
                if (MODE == 0) {
                    const int h = n_base >> 6, cc = (n_base & 63) + c4;
                    *(float4*)(out + ((size_t)(b * HH + h) * LL + l0 + r) * DKK + cc) = v;
                } else {
                    *(float4*)(out + (size_t)(m0 + r) * DD + n_base + c4) = v;
                }
            }
        }
        __syncthreads();
    }
}

// ================= scores: strips of 4 kt-tiles; Q loaded once; zero-fill masked ====
__global__ void __launch_bounds__(256, 2)
scores_mma(const float* __restrict__ q, const float* __restrict__ k,
           float* __restrict__ attn) {
    const int strip = blockIdx.x, qt = blockIdx.y, bhid = blockIdx.z;
    const int kt0 = strip * 4;
    const int q0 = qt * 128;
    extern __shared__ char sm[];
    const int tid = threadIdx.x, lane = tid & 31, wid = tid >> 5;
    const int warp_m = wid & 1, warp_n = wid >> 1;     // 2 x 4; warp tile 64x32

    float* attnb = attn + ((size_t)bhid * LL + q0) * LL;

    if (kt0 > qt) {
        // whole strip masked: stream zeros 128 x 512
        const float4 z = make_float4(0.f, 0.f, 0.f, 0.f);
        for (int u = tid; u < 128 * 128; u += 256) {
            const int r = u >> 7, c4 = (u & 127) << 2;
            *(float4*)(attnb + (size_t)r * LL + kt0 * 128 + c4) = z;
        }
        return;
    }

    // load Q tile once; prefetch K(kt0)
    load_split64((__nv_bfloat16*)(sm + SC_QH), (__nv_bfloat16*)(sm + SC_QL),
                 q + ((size_t)bhid * LL + q0) * DKK, DKK, tid);
    float4 kbuf[8];
    {
        const float* kb = k + ((size_t)bhid * LL + kt0 * 128) * DKK;
        #pragma unroll
        for (int i = 0; i < 8; i++) {
            const int u = tid + i * 256;
            kbuf[i] = *(const float4*)(kb + (size_t)(u >> 4) * DKK + ((u & 15) << 2));
        }
    }
    __syncthreads();

    float* stg = (float*)(sm + SC_STG);
    for (int kt = kt0; kt < kt0 + 4; kt++) {
        if (kt <= qt) {
            // store prefetched K into smem (split)
            #pragma unroll
            for (int i = 0; i < 8; i++) {
                const int u = tid + i * 256;
                const int r = u >> 4, c4 = (u & 15) << 2;
                uint2 hv, lv; cvt_split(kbuf[i], hv, lv);
                *(uint2*)((__nv_bfloat16*)(sm + SC_KH) + r * SPAD2 + c4) = hv;
                *(uint2*)((__nv_bfloat16*)(sm + SC_KL) + r * SPAD2 + c4) = lv;
            }
            __syncthreads();

            float acc[4][4][4] = {};
            block_mma<4, 4, SPAD2, 64>((__nv_bfloat16*)(sm + SC_QH), (__nv_bfloat16*)(sm + SC_QL),
                                       (__nv_bfloat16*)(sm + SC_KH), (__nv_bfloat16*)(sm + SC_KL),
                                       warp_m * 64, warp_n * 32, lane, acc);

            // prefetch next K during epilogue
            if (kt + 1 <= qt && kt + 1 < kt0 + 4) {
                const float* kb = k + ((size_t)bhid * LL + (kt + 1) * 128) * DKK;
                #pragma unroll
                for (int i = 0; i < 8; i++) {
                    const int u = tid + i * 256;
                    kbuf[i] = *(const float4*)(kb + (size_t)(u >> 4) * DKK + ((u & 15) << 2));
                }
            }
            __syncthreads();

            for (int g = 0; g < 4; g++) {
                if (warp_n == g) stage_group<4, 4>(stg, warp_m, 0, lane, acc, 0.125f);
                __syncthreads();
                for (int u = tid; u < 1024; u += 256) {
                    const int r = u >> 3, c4 = (u & 7) << 2;
                    float4 v = make_float4(stg[(size_t)r * 33 + c4 + 0], stg[(size_t)r * 33 + c4 + 1],
                                           stg[(size_t)r * 33 + c4 + 2], stg[(size_t)r * 33 + c4 + 3]);
                    *(float4*)(attnb + (size_t)r * LL + kt * 128 + g * 32 + c4) = v;
                }
                __syncthreads();
            }
        } else {
            // masked tile: zeros
            const float4 z = make_float4(0.f, 0.f, 0.f, 0.f);
            for (int u = tid; u < 128 * 32; u += 256) {
                const int r = u >> 5, c4 = (u & 31) << 2;
                *(float4*)(attnb + (size_t)r * LL + kt * 128 + c4) = z;
            }
        }
    }
}

// ================= O = P @ V (causal k-range, pipelined) =================
__global__ void __launch_bounds__(256, 2)
av_mma(const float* __restrict__ attn, const float* __restrict__ vt,
       float* __restrict__ oc) {
    const int qt = blockIdx.x, bhid = blockIdx.y;
    const int b = bhid >> 4, h = bhid & 15;
    extern __shared__ char sm[];
    const int tid = threadIdx.x, lane = tid & 31, wid = tid >> 5;
    const int warp_m = wid & 1, warp_n = wid >> 1;
    const int q0 = qt * 128;

    const float* Pb = attn + ((size_t)bhid * LL + q0) * LL;
    const float* Vb = vt + (size_t)bhid * DKK * LL;

    float acc[4][2][4] = {};
    float4 ra[4], rb[2];

    const int NK = (qt + 1) * 4;

    ldg_chunk<4>(ra, Pb, LL, tid);
    ldg_chunk<2>(rb, Vb, LL, tid);
    {
        char* s0 = sm;
        sts_chunk<4>(ra, (__nv_bfloat16*)(s0 + ST_AH), (__nv_bfloat16*)(s0 + ST_AL), tid);
        sts_chunk<2>(rb, (__nv_bfloat16*)(s0 + ST_BH), (__nv_bfloat16*)(s0 + ST_BL), tid);
    }
    ldg_chunk<4>(ra, Pb + 32, LL, tid);
    ldg_chunk<2>(rb, Vb + 32, LL, tid);
    __syncthreads();

    for (int k = 0; k < NK; k++) {
        char* cur = sm + (k & 1) * STAGE_BYTES;
        block_mma<4, 2, SPAD, 32>((__nv_bfloat16*)(cur + ST_AH), (__nv_bfloat16*)(cur + ST_AL),
                                  (__nv_bfloat16*)(cur + ST_BH), (__nv_bfloat16*)(cur + ST_BL),
                                  warp_m * 64, warp_n * 16, lane, acc);
        if (k + 1 < NK) {
            char* nxt = sm + ((k + 1) & 1) * STAGE_BYTES;
            sts_chunk<4>(ra, (__nv_bfloat16*)(nxt + ST_AH), (__nv_bfloat16*)(nxt + ST_AL), tid);
            sts_chunk<2>(rb, (__nv_bfloat16*)(nxt + ST_BH), (__nv_bfloat16*)(nxt + ST_BL), tid);
        }
        if (k + 2 < NK) {
            ldg_chunk<4>(ra, Pb + (k + 2) * 32, LL, tid);
            ldg_chunk<2>(rb, Vb + (k + 2) * 32, LL, tid);
        }
        __syncthreads();
    }

    float* stg = (float*)sm;
    for (int g = 0; g < 2; g++) {
        if ((warp_n >> 1) == g)
            stage_group<4, 2>(stg, warp_m, (warp_n & 1) * 16, lane, acc, 1.0f);
        __syncthreads();
        for (int u = tid; u < 1024; u += 256) {
            const int r = u >> 3, c4 = (u & 7) << 2;
            float4 v = make_float4(stg[(size_t)r * 33 + c4 + 0], stg[(size_t)r * 33 + c4 + 1],
                                   stg[(size_t)r * 33 + c4 + 2], stg[(size_t)r * 33 + c4 + 3]);
            *(float4*)(oc + (size_t)(b * LL + q0 + r) * DD + h * DKK + g * 32 + c4) = v;
        }
        __syncthreads();
    }
}

// ================= row softmax (causal, bounded to qt-tile-aligned end) ============
__global__ void softmax_kernel(float* __restrict__ attn) {
    const int row = blockIdx.x, bh = blockIdx.y;
    float* p = attn + ((size_t)bh * LL + row) * LL;
    const int valid = row + 1;
    const int nend = (((row >> 7) + 1) << 7);   // 128..2048, zeros beyond pre-written
    const int tid = threadIdx.x;

    __shared__ float sred[8];

    float4 v[2];
    float m = -3.4e38f;
    #pragma unroll
    for (int i = 0; i < 2; i++) {
        const int j = (tid + i * 256) * 4;
        if (j < nend) {
            v[i] = *(const float4*)(p + j);
            if (j + 0 < valid) m = fmaxf(m, v[i].x);
            if (j + 1 < valid) m = fmaxf(m, v[i].y);
            if (j + 2 < valid) m = fmaxf(m, v[i].z);
            if (j + 3 < valid) m = fmaxf(m, v[i].w);
        }
    }
    #pragma unroll
    for (int o = 16; o > 0; o >>= 1) m = fmaxf(m, __shfl_xor_sync(0xffffffff, m, o));
    if ((tid & 31) == 0) sred[tid >> 5] = m;
    __syncthreads();
    m = sred[0];
    #pragma unroll
    for (int w = 1; w < 8; w++) m = fmaxf(m, sred[w]);

    float sum = 0.0f;
    #pragma unroll
    for (int i = 0; i < 2; i++) {
        const int j = (tid + i * 256) * 4;
        if (j < nend) {
            v[i].x = (j + 0 < valid) ? __expf(v[i].x - m) : 0.0f;
            v[i].y = (j + 1 < valid) ? __expf(v[i].y - m) : 0.0f;
            v[i].z = (j + 2 < valid) ? __expf(v[i].z - m) : 0.0f;
            v[i].w = (j + 3 < valid) ? __expf(v[i].w - m) : 0.0f;
            sum += v[i].x + v[i].y + v[i].z + v[i].w;
        }
    }
    __syncthreads();
    #pragma unroll
    for (int o = 16; o > 0; o >>= 1) sum += __shfl_xor_sync(0xffffffff, sum, o);
    if ((tid & 31) == 0) sred[tid >> 5] = sum;
    __syncthreads();
    sum = 0.0f;
    #pragma unroll
    for (int w = 0; w < 8; w++) sum += sred[w];
    const float inv = 1.0f / sum;

    #pragma unroll
    for (int i = 0; i < 2; i++) {
        const int j = (tid + i * 256) * 4;
        if (j < nend) {
            float4 o4;
            o4.x = v[i].x * inv; o4.y = v[i].y * inv;
            o4.z = v[i].z * inv; o4.w = v[i].w * inv;
            *(float4*)(p + j) = o4;
        }
    }
}

// ---------------- launch ----------------
extern "C" void kernel_launch(void* const* d_in, const int* in_sizes, int n_in,
                              void* d_out, int out_size) {
    const float* x  = (const float*)d_in[0];
    const float* Wq = (const float*)d_in[2];
    const float* bq = (const float*)d_in[3];
    const float* Wk = (const float*)d_in[4];
    const float* bk = (const float*)d_in[5];
    const float* Wv = (const float*)d_in[6];
    const float* bv = (const float*)d_in[7];
    const float* Wo = (const float*)d_in[8];
    const float* bo = (const float*)d_in[9];
    float* out = (float*)d_out;

    const size_t out_elems  = (size_t)BB * LL * DD;
    const size_t attn_elems = (size_t)BH * LL * LL;

    float *q, *k, *vt, *oc, *attn;
    cudaGetSymbolAddress((void**)&q,  g_q);
    cudaGetSymbolAddress((void**)&k,  g_k);
    cudaGetSymbolAddress((void**)&vt, g_vt);
    cudaGetSymbolAddress((void**)&oc, g_oc);
    if ((size_t)out_size >= out_elems + attn_elems) {
        attn = out + out_elems;
    } else {
        cudaGetSymbolAddress((void**)&attn, g_attn_scratch);
    }

    cudaFuncSetAttribute(gemm_proj<0>, cudaFuncAttributeMaxDynamicSharedMemorySize, PIPE_SMEM);
    cudaFuncSetAttribute(gemm_proj<1>, cudaFuncAttributeMaxDynamicSharedMemorySize, PIPE_SMEM);
    cudaFuncSetAttribute(gemm_proj<2>, cudaFuncAttributeMaxDynamicSharedMemorySize, PIPE_SMEM);
    cudaFuncSetAttribute(scores_mma,   cudaFuncAttributeMaxDynamicSharedMemorySize, SC_SMEM);
    cudaFuncSetAttribute(av_mma,       cudaFuncAttributeMaxDynamicSharedMemorySize, PIPE_SMEM);

    dim3 projGrid(DD / 64, MROWS / 128);       // (16, 64)
    gemm_proj<0><<<projGrid, 256, PIPE_SMEM>>>(x, Wq, bq, q);
    gemm_proj<0><<<projGrid, 256, PIPE_SMEM>>>(x, Wk, bk, k);
    gemm_proj<1><<<projGrid, 256, PIPE_SMEM>>>(x, Wv, bv, vt);

    dim3 scoreGrid(4, LL / 128, BH);           // (4, 16, 64)
    scores_mma<<<scoreGrid, 256, SC_SMEM>>>(q, k, attn);

    dim3 smGrid(LL, BH);
    softmax_kernel<<<smGrid, 256>>>(attn);

    dim3 avGrid(LL / 128, BH);                 // (16, 64)
    av_mma<<<avGrid, 256, PIPE_SMEM>>>(attn, vt, oc);

    gemm_proj<2><<<projGrid, 256, PIPE_SMEM>>>(oc, Wo, bo, out);
}